// round 1
// baseline (speedup 1.0000x reference)
#include <cuda_runtime.h>
#include <math.h>

// ---------------------------------------------------------------------------
// Problem constants
// ---------------------------------------------------------------------------
#define B_   256
#define T_   64
#define L_   1024
#define S_   512
#define NC_  239
#define BT_  (B_ * T_)          // 16384
#define DIN_ 2048               // x feature dim
#define DSM_ 1280               // x_small feature dim
#define DCAT_ 2560              // feats(2048) | sfeats(512)

// ---------------------------------------------------------------------------
// Device scratch (allocation-free: __device__ globals)
// ---------------------------------------------------------------------------
__device__ float g_cat[(size_t)BT_ * DCAT_];   // [BT, 2560]  feats | sfeats
__device__ float g_gl [(size_t)BT_ * 4096];    // large-cell pre-gates (x part + biases)
__device__ float g_gs [(size_t)BT_ * 2048];    // small-cell pre-gates
__device__ float g_zs [(size_t)BT_ * 2];       // gate logits, s_t part + b_g
__device__ float g_gatesL[B_ * 4096];          // per-step full large gates
__device__ float g_gatesS[B_ * 2048];          // per-step full small gates
__device__ float g_hl[B_ * L_];
__device__ float g_cl[B_ * L_];
__device__ float g_hs[B_ * S_];
__device__ float g_cs[B_ * S_];
__device__ int   g_r[B_];                      // hard gate select per row

// ---------------------------------------------------------------------------
// Epilogue modes for the generic GEMM
// ---------------------------------------------------------------------------
#define EPI_BIAS   0   // C = acc + p0[n]
#define EPI_BNRELU 1   // C = relu((acc + p0[n]) * (p1[n]*rsqrt(1+eps)) + p2[n])
#define EPI_PRE    2   // C = acc + p0[m*ldp + n]   (pre-gates add)
#define EPI_BIAS2  3   // C = acc + p0[n] + p1[n]

// ---------------------------------------------------------------------------
// SIMT fp32 GEMM:  C[M,N] = A[M,K] @ W[N,K]^T  (+ epilogue)
// Tile: BM=128, BN=64, BK=16, 256 threads, 8x4 per thread.
// Requires: M%128==0, N%64==0, K%16==0, all row strides 16B-aligned.
// ---------------------------------------------------------------------------
template <int EPI>
__global__ void __launch_bounds__(256)
gemm128x64(const float* __restrict__ A, int lda,
           const float* __restrict__ W, int K,
           float* __restrict__ C, int ldc,
           const float* __restrict__ p0,
           const float* __restrict__ p1,
           const float* __restrict__ p2,
           int ldp)
{
    __shared__ float As[16][128];
    __shared__ float Bs[16][64];

    const int tid = threadIdx.x;
    const int m0  = blockIdx.y * 128;
    const int n0  = blockIdx.x * 64;
    const int tx  = tid & 15;    // column group: 16 groups x 4 cols
    const int ty  = tid >> 4;    // row group:    16 groups x 8 rows

    float acc[8][4];
#pragma unroll
    for (int i = 0; i < 8; ++i)
#pragma unroll
        for (int j = 0; j < 4; ++j) acc[i][j] = 0.0f;

    for (int k0 = 0; k0 < K; k0 += 16) {
        // ---- load A tile (128x16) : 2 float4 per thread ----
#pragma unroll
        for (int u = 0; u < 2; ++u) {
            int li = tid * 2 + u;          // 0..511 float4 slots
            int r  = li >> 2;              // tile row 0..127
            int kc = (li & 3) << 2;        // k offset 0/4/8/12
            float4 v = *(const float4*)(A + (size_t)(m0 + r) * lda + k0 + kc);
            As[kc + 0][r] = v.x; As[kc + 1][r] = v.y;
            As[kc + 2][r] = v.z; As[kc + 3][r] = v.w;
        }
        // ---- load W tile (64x16) : 1 float4 per thread ----
        {
            int li = tid;                  // 0..255
            int r  = li >> 2;              // tile row 0..63
            int kc = (li & 3) << 2;
            float4 v = *(const float4*)(W + (size_t)(n0 + r) * K + k0 + kc);
            Bs[kc + 0][r] = v.x; Bs[kc + 1][r] = v.y;
            Bs[kc + 2][r] = v.z; Bs[kc + 3][r] = v.w;
        }
        __syncthreads();

#pragma unroll
        for (int k = 0; k < 16; ++k) {
            float rm[8], rn[4];
#pragma unroll
            for (int i = 0; i < 8; ++i) rm[i] = As[k][ty * 8 + i];
#pragma unroll
            for (int j = 0; j < 4; ++j) rn[j] = Bs[k][tx * 4 + j];
#pragma unroll
            for (int i = 0; i < 8; ++i)
#pragma unroll
                for (int j = 0; j < 4; ++j)
                    acc[i][j] = fmaf(rm[i], rn[j], acc[i][j]);
        }
        __syncthreads();
    }

    const float bnm = rsqrtf(1.0f + 1e-5f);
#pragma unroll
    for (int i = 0; i < 8; ++i) {
        int m = m0 + ty * 8 + i;
#pragma unroll
        for (int j = 0; j < 4; ++j) {
            int n = n0 + tx * 4 + j;
            float v = acc[i][j];
            if (EPI == EPI_BIAS)   v += p0[n];
            if (EPI == EPI_BIAS2)  v += p0[n] + p1[n];
            if (EPI == EPI_BNRELU) {
                v = (v + p0[n]) * (p1[n] * bnm) + p2[n];
                v = fmaxf(v, 0.0f);
            }
            if (EPI == EPI_PRE)    v += p0[(size_t)m * ldp + n];
            C[(size_t)m * ldc + n] = v;
        }
    }
}

// ---------------------------------------------------------------------------
// Zero initial LSTM states
// ---------------------------------------------------------------------------
__global__ void init_states()
{
    int idx = blockIdx.x * blockDim.x + threadIdx.x;
    if (idx < B_ * L_) { g_hl[idx] = 0.0f; g_cl[idx] = 0.0f; }
    if (idx < B_ * S_) { g_hs[idx] = 0.0f; g_cs[idx] = 0.0f; }
}

// ---------------------------------------------------------------------------
// zs[m, j] = sum_{k<512} sfeats[m,k] * W_g[j,k] + b_g[j]   (time-parallel)
// one block (128 threads) per row m
// ---------------------------------------------------------------------------
__global__ void zs_kernel(const float* __restrict__ Wg, const float* __restrict__ bg)
{
    __shared__ float red0[128], red1[128];
    int m = blockIdx.x;
    const float* s = g_cat + (size_t)m * DCAT_ + 2048;
    float a0 = 0.0f, a1 = 0.0f;
    for (int k = threadIdx.x; k < 512; k += 128) {
        float sv = s[k];
        a0 = fmaf(sv, Wg[k], a0);
        a1 = fmaf(sv, Wg[DCAT_ + k], a1);
    }
    red0[threadIdx.x] = a0; red1[threadIdx.x] = a1;
    __syncthreads();
    for (int st = 64; st > 0; st >>= 1) {
        if (threadIdx.x < st) {
            red0[threadIdx.x] += red0[threadIdx.x + st];
            red1[threadIdx.x] += red1[threadIdx.x + st];
        }
        __syncthreads();
    }
    if (threadIdx.x == 0) {
        g_zs[2 * m + 0] = red0[0] + bg[0];
        g_zs[2 * m + 1] = red1[0] + bg[1];
    }
}

// ---------------------------------------------------------------------------
// Per-step gate: z_j = zs + W_g[j,512:1536].h_l + W_g[j,1536:2560].c_l
// hard argmax (ties -> 0), write r_stack and select bit.
// one block (128 threads) per batch row
// ---------------------------------------------------------------------------
__global__ void gate_kernel(const float* __restrict__ Wg, int t,
                            float* __restrict__ out_r)
{
    __shared__ float red0[128], red1[128];
    int b = blockIdx.x;
    const float* hl  = g_hl + b * L_;
    const float* cl  = g_cl + b * L_;
    const float* w0  = Wg + 512;           // row 0, h part
    const float* w1  = Wg + DCAT_ + 512;   // row 1, h part
    float a0 = 0.0f, a1 = 0.0f;
    for (int k = threadIdx.x; k < L_; k += 128) {
        float hv = hl[k], cv = cl[k];
        a0 = fmaf(hv, w0[k], a0); a0 = fmaf(cv, w0[L_ + k], a0);
        a1 = fmaf(hv, w1[k], a1); a1 = fmaf(cv, w1[L_ + k], a1);
    }
    red0[threadIdx.x] = a0; red1[threadIdx.x] = a1;
    __syncthreads();
    for (int st = 64; st > 0; st >>= 1) {
        if (threadIdx.x < st) {
            red0[threadIdx.x] += red0[threadIdx.x + st];
            red1[threadIdx.x] += red1[threadIdx.x + st];
        }
        __syncthreads();
    }
    if (threadIdx.x == 0) {
        float z0 = g_zs[(size_t)(b * T_ + t) * 2 + 0] + red0[0];
        float z1 = g_zs[(size_t)(b * T_ + t) * 2 + 1] + red1[0];
        int r = (z0 >= z1) ? 0 : 1;   // jnp.argmax: first max wins
        g_r[b] = r;
        out_r[(size_t)t * B_ * 2 + b * 2 + 0] = (r == 0) ? 1.0f : 0.0f;
        out_r[(size_t)t * B_ * 2 + b * 2 + 1] = (r == 1) ? 1.0f : 0.0f;
    }
}

__device__ __forceinline__ float sigf(float x) { return 1.0f / (1.0f + expf(-x)); }

// ---------------------------------------------------------------------------
// Small-cell pointwise: consumes g_gatesS, updates g_hs / g_cs in place
// ---------------------------------------------------------------------------
__global__ void lstm_small_pw()
{
    int idx = blockIdx.x * blockDim.x + threadIdx.x;   // B_*S_
    int b = idx >> 9, n = idx & (S_ - 1);
    const float* g = g_gatesS + b * 2048;
    float i = sigf(g[n]);
    float f = sigf(g[S_ + n]);
    float gg = tanhf(g[2 * S_ + n]);
    float o = sigf(g[3 * S_ + n]);
    float c2 = f * g_cs[idx] + i * gg;
    g_cs[idx] = c2;
    g_hs[idx] = o * tanhf(c2);
}

// ---------------------------------------------------------------------------
// Large-cell pointwise + hard gated select (in place; per-element read->write)
// ---------------------------------------------------------------------------
__global__ void lstm_large_pw()
{
    int idx = blockIdx.x * blockDim.x + threadIdx.x;   // B_*L_
    int b = idx >> 10, n = idx & (L_ - 1);
    const float* g = g_gatesL + b * 4096;
    float i = sigf(g[n]);
    float f = sigf(g[L_ + n]);
    float gg = tanhf(g[2 * L_ + n]);
    float o = sigf(g[3 * L_ + n]);
    float cold = g_cl[idx], hold = g_hl[idx];
    float c2 = f * cold + i * gg;
    float h2 = o * tanhf(c2);
    if (g_r[b] == 0) {
        g_hl[idx] = h2;
        g_cl[idx] = c2;
    } else {
        g_hl[idx] = (n < S_) ? g_hs[b * S_ + n] : hold;
        g_cl[idx] = (n < S_) ? g_cs[b * S_ + n] : cold;
    }
}

// ---------------------------------------------------------------------------
// Classifier: logits[b,n] = h_l[b,:] . W_c[n,:] + b_c[n]
// one block per batch row, thread n computes one output class
// ---------------------------------------------------------------------------
__global__ void classifier_kernel(const float* __restrict__ Wc,
                                  const float* __restrict__ bc,
                                  float* __restrict__ out)
{
    __shared__ float sh[L_];
    int b = blockIdx.x;
    for (int k = threadIdx.x; k < L_; k += blockDim.x) sh[k] = g_hl[b * L_ + k];
    __syncthreads();
    int n = threadIdx.x;
    if (n < NC_) {
        float a = bc[n];
        const float* w = Wc + (size_t)n * L_;
        for (int k = 0; k < L_; ++k) a = fmaf(sh[k], w[k], a);
        out[(size_t)b * NC_ + n] = a;
    }
}

// ---------------------------------------------------------------------------
// Host launcher
// ---------------------------------------------------------------------------
extern "C" void kernel_launch(void* const* d_in, const int* in_sizes, int n_in,
                              void* d_out, int out_size)
{
    const float* x      = (const float*)d_in[0];
    const float* xs     = (const float*)d_in[1];
    const float* W_p    = (const float*)d_in[2];
    const float* b_p    = (const float*)d_in[3];
    const float* g_p    = (const float*)d_in[4];
    const float* be_p   = (const float*)d_in[5];
    const float* W_s    = (const float*)d_in[6];
    const float* b_s    = (const float*)d_in[7];
    const float* g_s    = (const float*)d_in[8];
    const float* be_s   = (const float*)d_in[9];
    const float* Wih_l  = (const float*)d_in[10];
    const float* Whh_l  = (const float*)d_in[11];
    const float* bih_l  = (const float*)d_in[12];
    const float* bhh_l  = (const float*)d_in[13];
    const float* Wih_s  = (const float*)d_in[14];
    const float* Whh_s  = (const float*)d_in[15];
    const float* bih_s  = (const float*)d_in[16];
    const float* bhh_s  = (const float*)d_in[17];
    const float* W_g    = (const float*)d_in[18];
    const float* b_g    = (const float*)d_in[19];
    const float* W_c    = (const float*)d_in[20];
    const float* b_c    = (const float*)d_in[21];

    float* out        = (float*)d_out;
    float* out_logits = out;                       // [B, NC]
    float* out_r      = out + (size_t)B_ * NC_;    // [T, B, 2]

    // Cache device-symbol addresses (first call is uncaptured).
    static float *p_cat = nullptr, *p_gl = nullptr, *p_gs = nullptr,
                 *p_gatesL = nullptr, *p_gatesS = nullptr,
                 *p_hl = nullptr, *p_hs = nullptr;
    if (!p_cat) {
        cudaGetSymbolAddress((void**)&p_cat,    g_cat);
        cudaGetSymbolAddress((void**)&p_gl,     g_gl);
        cudaGetSymbolAddress((void**)&p_gs,     g_gs);
        cudaGetSymbolAddress((void**)&p_gatesL, g_gatesL);
        cudaGetSymbolAddress((void**)&p_gatesS, g_gatesS);
        cudaGetSymbolAddress((void**)&p_hl,     g_hl);
        cudaGetSymbolAddress((void**)&p_hs,     g_hs);
    }

    // ---- init states ----
    init_states<<<(B_ * L_ + 255) / 256, 256>>>();

    // ---- phase 1: time-parallel GEMMs ----
    // feats = relu(bn(x @ W_p^T + b_p))  -> cat[:, :2048]
    gemm128x64<EPI_BNRELU><<<dim3(DIN_ / 64, BT_ / 128), 256>>>(
        x, DIN_, W_p, DIN_, p_cat, DCAT_, b_p, g_p, be_p, 0);
    // sfeats = relu(bn(x_small @ W_s^T + b_s)) -> cat[:, 2048:]
    gemm128x64<EPI_BNRELU><<<dim3(S_ / 64, BT_ / 128), 256>>>(
        xs, DSM_, W_s, DSM_, p_cat + 2048, DCAT_, b_s, g_s, be_s, 0);
    // large pre-gates: cat @ Wih_l^T + bih_l + bhh_l
    gemm128x64<EPI_BIAS2><<<dim3(4096 / 64, BT_ / 128), 256>>>(
        p_cat, DCAT_, Wih_l, DCAT_, p_gl, 4096, bih_l, bhh_l, nullptr, 0);
    // small pre-gates: sfeats @ Wih_s^T + bih_s + bhh_s
    gemm128x64<EPI_BIAS2><<<dim3(2048 / 64, BT_ / 128), 256>>>(
        p_cat + 2048, DCAT_, Wih_s, S_, p_gs, 2048, bih_s, bhh_s, nullptr, 0);
    // gate logits, s_t part
    zs_kernel<<<BT_, 128>>>(W_g, b_g);

    // ---- phase 2: sequential recurrence ----
    for (int t = 0; t < T_; ++t) {
        // small recurrent GEMM + pre-gates
        gemm128x64<EPI_PRE><<<dim3(2048 / 64, B_ / 128), 256>>>(
            p_hs, S_, Whh_s, S_, p_gatesS, 2048,
            p_gs + (size_t)t * 2048, nullptr, nullptr, T_ * 2048);
        lstm_small_pw<<<(B_ * S_) / 256, 256>>>();
        // hard gate on OLD large state
        gate_kernel<<<B_, 128>>>(W_g, t, out_r);
        // large recurrent GEMM + pre-gates
        gemm128x64<EPI_PRE><<<dim3(4096 / 64, B_ / 128), 256>>>(
            p_hl, L_, Whh_l, L_, p_gatesL, 4096,
            p_gl + (size_t)t * 4096, nullptr, nullptr, T_ * 4096);
        lstm_large_pw<<<(B_ * L_) / 256, 256>>>();
    }

    // ---- classifier ----
    classifier_kernel<<<B_, 256>>>(W_c, b_c, out_logits);
}

// round 2
// speedup vs baseline: 1.1625x; 1.1625x over previous
#include <cuda_runtime.h>
#include <math.h>

// ---------------------------------------------------------------------------
// Problem constants
// ---------------------------------------------------------------------------
#define B_   256
#define T_   64
#define L_   1024
#define S_   512
#define NC_  239
#define BT_  (B_ * T_)          // 16384
#define DIN_ 2048               // x feature dim
#define DSM_ 1280               // x_small feature dim
#define DCAT_ 2560              // feats(2048) | sfeats(512)

// ---------------------------------------------------------------------------
// Device scratch (allocation-free: __device__ globals)
// ---------------------------------------------------------------------------
__device__ float g_cat[(size_t)BT_ * DCAT_];   // [BT, 2560]  feats | sfeats
__device__ float g_gl [(size_t)BT_ * 4096];    // large-cell pre-gates (x part + biases)
__device__ float g_gs [(size_t)BT_ * 2048];    // small-cell pre-gates
__device__ float g_zs [(size_t)BT_ * 2];       // gate logits, s_t part + b_g
__device__ float g_gatesL[B_ * 4096];          // per-step full large gates
__device__ float g_gatesS[B_ * 2048];          // per-step full small gates
__device__ float g_hl[B_ * L_];
__device__ float g_cl[B_ * L_];
__device__ float g_hs[B_ * S_];
__device__ float g_cs[B_ * S_];
__device__ int   g_r[B_];                      // hard gate select per row

// ---------------------------------------------------------------------------
// Epilogue modes
// ---------------------------------------------------------------------------
#define EPI_BIAS   0   // C = acc + p0[n]
#define EPI_BNRELU 1   // C = relu((acc + p0[n]) * (p1[n]*rsqrt(1+eps)) + p2[n])
#define EPI_PRE    2   // C = acc + p0[m*ldp + n]   (pre-gates add)
#define EPI_BIAS2  3   // C = acc + p0[n] + p1[n]

// ===========================================================================
// Phase-1 GEMM: C[M,N] = A[M,K] @ W[N,K]^T  (+ epilogue)
// Tile 128x128, BK=16, 256 threads, 8x8/thread, register-prefetch
// double-buffered smem (one __syncthreads per BK slab).
// Requires M%128==0, N%128==0, K%16==0.
// ===========================================================================
#define SMP 132   // padded smem row (floats): kills STS bank conflicts, 16B aligned

template <int EPI>
__global__ void __launch_bounds__(256, 2)
gemm128x128(const float* __restrict__ A, int lda,
            const float* __restrict__ W, int K,
            float* __restrict__ C, int ldc,
            const float* __restrict__ p0,
            const float* __restrict__ p1,
            const float* __restrict__ p2,
            int ldp)
{
    __shared__ float As[2][16][SMP];
    __shared__ float Bs[2][16][SMP];

    const int tid  = threadIdx.x;
    const int m0   = blockIdx.y * 128;
    const int n0   = blockIdx.x * 128;
    const int wid  = tid >> 5, lane = tid & 31;
    const int wm   = wid & 3,  wn   = wid >> 2;   // 4 x 2 warp grid
    const int lm   = lane & 3, ln   = lane >> 2;  // 4 x 8 lane grid
    const int tm   = wm * 32 + lm * 8;            // thread m base (0..120)
    const int tn   = wn * 64 + ln * 8;            // thread n base (0..120)

    // global->reg load plan: 2 float4 of A and 2 of W per thread per slab
    // li = u*256 + tid ; row = li>>2 (0..127), kc = (li&3)*4
    const int r0  = tid >> 2;            // u=0 rows 0..63
    const int r1  = r0 + 64;             // u=1 rows 64..127
    const int kc_ = (tid & 3) << 2;      // 0/4/8/12

    const float* Arow0 = A + (size_t)(m0 + r0) * lda + kc_;
    const float* Arow1 = A + (size_t)(m0 + r1) * lda + kc_;
    const float* Wrow0 = W + (size_t)(n0 + r0) * K + kc_;
    const float* Wrow1 = W + (size_t)(n0 + r1) * K + kc_;

    float acc[8][8];
#pragma unroll
    for (int i = 0; i < 8; ++i)
#pragma unroll
        for (int j = 0; j < 8; ++j) acc[i][j] = 0.0f;

    float4 pa0, pa1, pb0, pb1;

    // ---- preload slab 0 ----
    pa0 = *(const float4*)(Arow0);
    pa1 = *(const float4*)(Arow1);
    pb0 = *(const float4*)(Wrow0);
    pb1 = *(const float4*)(Wrow1);
    {
        As[0][kc_ + 0][r0] = pa0.x; As[0][kc_ + 1][r0] = pa0.y;
        As[0][kc_ + 2][r0] = pa0.z; As[0][kc_ + 3][r0] = pa0.w;
        As[0][kc_ + 0][r1] = pa1.x; As[0][kc_ + 1][r1] = pa1.y;
        As[0][kc_ + 2][r1] = pa1.z; As[0][kc_ + 3][r1] = pa1.w;
        Bs[0][kc_ + 0][r0] = pb0.x; Bs[0][kc_ + 1][r0] = pb0.y;
        Bs[0][kc_ + 2][r0] = pb0.z; Bs[0][kc_ + 3][r0] = pb0.w;
        Bs[0][kc_ + 0][r1] = pb1.x; Bs[0][kc_ + 1][r1] = pb1.y;
        Bs[0][kc_ + 2][r1] = pb1.z; Bs[0][kc_ + 3][r1] = pb1.w;
    }
    __syncthreads();

    const int ntiles = K >> 4;
    int cur = 0;
    for (int it = 1; it < ntiles; ++it) {
        // prefetch next slab (hides DRAM/L2 latency behind compute)
        const int k0 = it << 4;
        pa0 = *(const float4*)(Arow0 + k0);
        pa1 = *(const float4*)(Arow1 + k0);
        pb0 = *(const float4*)(Wrow0 + k0);
        pb1 = *(const float4*)(Wrow1 + k0);

        // compute current slab
#pragma unroll
        for (int k = 0; k < 16; ++k) {
            float rm[8], rn[8];
            *(float4*)&rm[0] = *(const float4*)&As[cur][k][tm];
            *(float4*)&rm[4] = *(const float4*)&As[cur][k][tm + 4];
            *(float4*)&rn[0] = *(const float4*)&Bs[cur][k][tn];
            *(float4*)&rn[4] = *(const float4*)&Bs[cur][k][tn + 4];
#pragma unroll
            for (int i = 0; i < 8; ++i)
#pragma unroll
                for (int j = 0; j < 8; ++j)
                    acc[i][j] = fmaf(rm[i], rn[j], acc[i][j]);
        }

        // stash prefetched slab into the other buffer
        const int nxt = cur ^ 1;
        As[nxt][kc_ + 0][r0] = pa0.x; As[nxt][kc_ + 1][r0] = pa0.y;
        As[nxt][kc_ + 2][r0] = pa0.z; As[nxt][kc_ + 3][r0] = pa0.w;
        As[nxt][kc_ + 0][r1] = pa1.x; As[nxt][kc_ + 1][r1] = pa1.y;
        As[nxt][kc_ + 2][r1] = pa1.z; As[nxt][kc_ + 3][r1] = pa1.w;
        Bs[nxt][kc_ + 0][r0] = pb0.x; Bs[nxt][kc_ + 1][r0] = pb0.y;
        Bs[nxt][kc_ + 2][r0] = pb0.z; Bs[nxt][kc_ + 3][r0] = pb0.w;
        Bs[nxt][kc_ + 0][r1] = pb1.x; Bs[nxt][kc_ + 1][r1] = pb1.y;
        Bs[nxt][kc_ + 2][r1] = pb1.z; Bs[nxt][kc_ + 3][r1] = pb1.w;
        __syncthreads();
        cur = nxt;
    }

    // last slab
#pragma unroll
    for (int k = 0; k < 16; ++k) {
        float rm[8], rn[8];
        *(float4*)&rm[0] = *(const float4*)&As[cur][k][tm];
        *(float4*)&rm[4] = *(const float4*)&As[cur][k][tm + 4];
        *(float4*)&rn[0] = *(const float4*)&Bs[cur][k][tn];
        *(float4*)&rn[4] = *(const float4*)&Bs[cur][k][tn + 4];
#pragma unroll
        for (int i = 0; i < 8; ++i)
#pragma unroll
            for (int j = 0; j < 8; ++j)
                acc[i][j] = fmaf(rm[i], rn[j], acc[i][j]);
    }

    // epilogue
    const float bnm = rsqrtf(1.0f + 1e-5f);
#pragma unroll
    for (int i = 0; i < 8; ++i) {
        const int m = m0 + tm + i;
        float* crow = C + (size_t)m * ldc + n0 + tn;
#pragma unroll
        for (int j = 0; j < 8; ++j) {
            const int n = n0 + tn + j;
            float v = acc[i][j];
            if (EPI == EPI_BIAS)   v += p0[n];
            if (EPI == EPI_BIAS2)  v += p0[n] + p1[n];
            if (EPI == EPI_BNRELU) {
                v = (v + p0[n]) * (p1[n] * bnm) + p2[n];
                v = fmaxf(v, 0.0f);
            }
            if (EPI == EPI_PRE)    v += p0[(size_t)m * ldp + n];
            crow[j] = v;
        }
    }
}

// ===========================================================================
// Phase-2 GEMM (small M): 128x64 tile, BK=16, 256 threads, 8x4/thread
// ===========================================================================
template <int EPI>
__global__ void __launch_bounds__(256)
gemm128x64(const float* __restrict__ A, int lda,
           const float* __restrict__ W, int K,
           float* __restrict__ C, int ldc,
           const float* __restrict__ p0,
           const float* __restrict__ p1,
           const float* __restrict__ p2,
           int ldp)
{
    __shared__ float As[16][128];
    __shared__ float Bs[16][64];

    const int tid = threadIdx.x;
    const int m0  = blockIdx.y * 128;
    const int n0  = blockIdx.x * 64;
    const int tx  = tid & 15;
    const int ty  = tid >> 4;

    float acc[8][4];
#pragma unroll
    for (int i = 0; i < 8; ++i)
#pragma unroll
        for (int j = 0; j < 4; ++j) acc[i][j] = 0.0f;

    for (int k0 = 0; k0 < K; k0 += 16) {
#pragma unroll
        for (int u = 0; u < 2; ++u) {
            int li = tid * 2 + u;
            int r  = li >> 2;
            int kc = (li & 3) << 2;
            float4 v = *(const float4*)(A + (size_t)(m0 + r) * lda + k0 + kc);
            As[kc + 0][r] = v.x; As[kc + 1][r] = v.y;
            As[kc + 2][r] = v.z; As[kc + 3][r] = v.w;
        }
        {
            int li = tid;
            int r  = li >> 2;
            int kc = (li & 3) << 2;
            float4 v = *(const float4*)(W + (size_t)(n0 + r) * K + k0 + kc);
            Bs[kc + 0][r] = v.x; Bs[kc + 1][r] = v.y;
            Bs[kc + 2][r] = v.z; Bs[kc + 3][r] = v.w;
        }
        __syncthreads();

#pragma unroll
        for (int k = 0; k < 16; ++k) {
            float rm[8], rn[4];
#pragma unroll
            for (int i = 0; i < 8; ++i) rm[i] = As[k][ty * 8 + i];
#pragma unroll
            for (int j = 0; j < 4; ++j) rn[j] = Bs[k][tx * 4 + j];
#pragma unroll
            for (int i = 0; i < 8; ++i)
#pragma unroll
                for (int j = 0; j < 4; ++j)
                    acc[i][j] = fmaf(rm[i], rn[j], acc[i][j]);
        }
        __syncthreads();
    }

    const float bnm = rsqrtf(1.0f + 1e-5f);
#pragma unroll
    for (int i = 0; i < 8; ++i) {
        int m = m0 + ty * 8 + i;
#pragma unroll
        for (int j = 0; j < 4; ++j) {
            int n = n0 + tx * 4 + j;
            float v = acc[i][j];
            if (EPI == EPI_BIAS)   v += p0[n];
            if (EPI == EPI_BIAS2)  v += p0[n] + p1[n];
            if (EPI == EPI_BNRELU) {
                v = (v + p0[n]) * (p1[n] * bnm) + p2[n];
                v = fmaxf(v, 0.0f);
            }
            if (EPI == EPI_PRE)    v += p0[(size_t)m * ldp + n];
            C[(size_t)m * ldc + n] = v;
        }
    }
}

// ---------------------------------------------------------------------------
// Zero initial LSTM states
// ---------------------------------------------------------------------------
__global__ void init_states()
{
    int idx = blockIdx.x * blockDim.x + threadIdx.x;
    if (idx < B_ * L_) { g_hl[idx] = 0.0f; g_cl[idx] = 0.0f; }
    if (idx < B_ * S_) { g_hs[idx] = 0.0f; g_cs[idx] = 0.0f; }
}

// ---------------------------------------------------------------------------
// zs[m, j] = sum_{k<512} sfeats[m,k] * W_g[j,k] + b_g[j]   (time-parallel)
// ---------------------------------------------------------------------------
__global__ void zs_kernel(const float* __restrict__ Wg, const float* __restrict__ bg)
{
    __shared__ float red0[128], red1[128];
    int m = blockIdx.x;
    const float* s = g_cat + (size_t)m * DCAT_ + 2048;
    float a0 = 0.0f, a1 = 0.0f;
    for (int k = threadIdx.x; k < 512; k += 128) {
        float sv = s[k];
        a0 = fmaf(sv, Wg[k], a0);
        a1 = fmaf(sv, Wg[DCAT_ + k], a1);
    }
    red0[threadIdx.x] = a0; red1[threadIdx.x] = a1;
    __syncthreads();
    for (int st = 64; st > 0; st >>= 1) {
        if (threadIdx.x < st) {
            red0[threadIdx.x] += red0[threadIdx.x + st];
            red1[threadIdx.x] += red1[threadIdx.x + st];
        }
        __syncthreads();
    }
    if (threadIdx.x == 0) {
        g_zs[2 * m + 0] = red0[0] + bg[0];
        g_zs[2 * m + 1] = red1[0] + bg[1];
    }
}

// ---------------------------------------------------------------------------
// Per-step gate: hard argmax (ties -> 0), write r_stack and select bit.
// ---------------------------------------------------------------------------
__global__ void gate_kernel(const float* __restrict__ Wg, int t,
                            float* __restrict__ out_r)
{
    __shared__ float red0[128], red1[128];
    int b = blockIdx.x;
    const float* hl  = g_hl + b * L_;
    const float* cl  = g_cl + b * L_;
    const float* w0  = Wg + 512;
    const float* w1  = Wg + DCAT_ + 512;
    float a0 = 0.0f, a1 = 0.0f;
    for (int k = threadIdx.x; k < L_; k += 128) {
        float hv = hl[k], cv = cl[k];
        a0 = fmaf(hv, w0[k], a0); a0 = fmaf(cv, w0[L_ + k], a0);
        a1 = fmaf(hv, w1[k], a1); a1 = fmaf(cv, w1[L_ + k], a1);
    }
    red0[threadIdx.x] = a0; red1[threadIdx.x] = a1;
    __syncthreads();
    for (int st = 64; st > 0; st >>= 1) {
        if (threadIdx.x < st) {
            red0[threadIdx.x] += red0[threadIdx.x + st];
            red1[threadIdx.x] += red1[threadIdx.x + st];
        }
        __syncthreads();
    }
    if (threadIdx.x == 0) {
        float z0 = g_zs[(size_t)(b * T_ + t) * 2 + 0] + red0[0];
        float z1 = g_zs[(size_t)(b * T_ + t) * 2 + 1] + red1[0];
        int r = (z0 >= z1) ? 0 : 1;
        g_r[b] = r;
        out_r[(size_t)t * B_ * 2 + b * 2 + 0] = (r == 0) ? 1.0f : 0.0f;
        out_r[(size_t)t * B_ * 2 + b * 2 + 1] = (r == 1) ? 1.0f : 0.0f;
    }
}

__device__ __forceinline__ float sigf(float x) { return 1.0f / (1.0f + expf(-x)); }

__global__ void lstm_small_pw()
{
    int idx = blockIdx.x * blockDim.x + threadIdx.x;
    int b = idx >> 9, n = idx & (S_ - 1);
    const float* g = g_gatesS + b * 2048;
    float i = sigf(g[n]);
    float f = sigf(g[S_ + n]);
    float gg = tanhf(g[2 * S_ + n]);
    float o = sigf(g[3 * S_ + n]);
    float c2 = f * g_cs[idx] + i * gg;
    g_cs[idx] = c2;
    g_hs[idx] = o * tanhf(c2);
}

__global__ void lstm_large_pw()
{
    int idx = blockIdx.x * blockDim.x + threadIdx.x;
    int b = idx >> 10, n = idx & (L_ - 1);
    const float* g = g_gatesL + b * 4096;
    float i = sigf(g[n]);
    float f = sigf(g[L_ + n]);
    float gg = tanhf(g[2 * L_ + n]);
    float o = sigf(g[3 * L_ + n]);
    float cold = g_cl[idx], hold = g_hl[idx];
    float c2 = f * cold + i * gg;
    float h2 = o * tanhf(c2);
    if (g_r[b] == 0) {
        g_hl[idx] = h2;
        g_cl[idx] = c2;
    } else {
        g_hl[idx] = (n < S_) ? g_hs[b * S_ + n] : hold;
        g_cl[idx] = (n < S_) ? g_cs[b * S_ + n] : cold;
    }
}

__global__ void classifier_kernel(const float* __restrict__ Wc,
                                  const float* __restrict__ bc,
                                  float* __restrict__ out)
{
    __shared__ float sh[L_];
    int b = blockIdx.x;
    for (int k = threadIdx.x; k < L_; k += blockDim.x) sh[k] = g_hl[b * L_ + k];
    __syncthreads();
    int n = threadIdx.x;
    if (n < NC_) {
        float a = bc[n];
        const float* w = Wc + (size_t)n * L_;
        for (int k = 0; k < L_; ++k) a = fmaf(sh[k], w[k], a);
        out[(size_t)b * NC_ + n] = a;
    }
}

// ---------------------------------------------------------------------------
// Host launcher
// ---------------------------------------------------------------------------
extern "C" void kernel_launch(void* const* d_in, const int* in_sizes, int n_in,
                              void* d_out, int out_size)
{
    const float* x      = (const float*)d_in[0];
    const float* xs     = (const float*)d_in[1];
    const float* W_p    = (const float*)d_in[2];
    const float* b_p    = (const float*)d_in[3];
    const float* g_p    = (const float*)d_in[4];
    const float* be_p   = (const float*)d_in[5];
    const float* W_s    = (const float*)d_in[6];
    const float* b_s    = (const float*)d_in[7];
    const float* g_s    = (const float*)d_in[8];
    const float* be_s   = (const float*)d_in[9];
    const float* Wih_l  = (const float*)d_in[10];
    const float* Whh_l  = (const float*)d_in[11];
    const float* bih_l  = (const float*)d_in[12];
    const float* bhh_l  = (const float*)d_in[13];
    const float* Wih_s  = (const float*)d_in[14];
    const float* Whh_s  = (const float*)d_in[15];
    const float* bih_s  = (const float*)d_in[16];
    const float* bhh_s  = (const float*)d_in[17];
    const float* W_g    = (const float*)d_in[18];
    const float* b_g    = (const float*)d_in[19];
    const float* W_c    = (const float*)d_in[20];
    const float* b_c    = (const float*)d_in[21];

    float* out        = (float*)d_out;
    float* out_logits = out;                       // [B, NC]
    float* out_r      = out + (size_t)B_ * NC_;    // [T, B, 2]

    static float *p_cat = nullptr, *p_gl = nullptr, *p_gs = nullptr,
                 *p_gatesL = nullptr, *p_gatesS = nullptr,
                 *p_hl = nullptr, *p_hs = nullptr;
    if (!p_cat) {
        cudaGetSymbolAddress((void**)&p_cat,    g_cat);
        cudaGetSymbolAddress((void**)&p_gl,     g_gl);
        cudaGetSymbolAddress((void**)&p_gs,     g_gs);
        cudaGetSymbolAddress((void**)&p_gatesL, g_gatesL);
        cudaGetSymbolAddress((void**)&p_gatesS, g_gatesS);
        cudaGetSymbolAddress((void**)&p_hl,     g_hl);
        cudaGetSymbolAddress((void**)&p_hs,     g_hs);
    }

    // ---- init states ----
    init_states<<<(B_ * L_ + 255) / 256, 256>>>();

    // ---- phase 1: time-parallel GEMMs (128x128 double-buffered) ----
    gemm128x128<EPI_BNRELU><<<dim3(DIN_ / 128, BT_ / 128), 256>>>(
        x, DIN_, W_p, DIN_, p_cat, DCAT_, b_p, g_p, be_p, 0);
    gemm128x128<EPI_BNRELU><<<dim3(S_ / 128, BT_ / 128), 256>>>(
        xs, DSM_, W_s, DSM_, p_cat + 2048, DCAT_, b_s, g_s, be_s, 0);
    gemm128x128<EPI_BIAS2><<<dim3(4096 / 128, BT_ / 128), 256>>>(
        p_cat, DCAT_, Wih_l, DCAT_, p_gl, 4096, bih_l, bhh_l, nullptr, 0);
    gemm128x128<EPI_BIAS2><<<dim3(2048 / 128, BT_ / 128), 256>>>(
        p_cat + 2048, DCAT_, Wih_s, S_, p_gs, 2048, bih_s, bhh_s, nullptr, 0);
    zs_kernel<<<BT_, 128>>>(W_g, b_g);

    // ---- phase 2: sequential recurrence ----
    for (int t = 0; t < T_; ++t) {
        gemm128x64<EPI_PRE><<<dim3(2048 / 64, B_ / 128), 256>>>(
            p_hs, S_, Whh_s, S_, p_gatesS, 2048,
            p_gs + (size_t)t * 2048, nullptr, nullptr, T_ * 2048);
        lstm_small_pw<<<(B_ * S_) / 256, 256>>>();
        gate_kernel<<<B_, 128>>>(W_g, t, out_r);
        gemm128x64<EPI_PRE><<<dim3(4096 / 64, B_ / 128), 256>>>(
            p_hl, L_, Whh_l, L_, p_gatesL, 4096,
            p_gl + (size_t)t * 4096, nullptr, nullptr, T_ * 4096);
        lstm_large_pw<<<(B_ * L_) / 256, 256>>>();
    }

    // ---- classifier ----
    classifier_kernel<<<B_, 256>>>(W_c, b_c, out_logits);
}

// round 5
// speedup vs baseline: 1.5041x; 1.2939x over previous
#include <cuda_runtime.h>
#include <cuda_bf16.h>
#include <math.h>
#include <stdint.h>

// ---------------------------------------------------------------------------
// Problem constants
// ---------------------------------------------------------------------------
#define B_   256
#define T_   64
#define L_   1024
#define S_   512
#define NC_  239
#define BT_  (B_ * T_)          // 16384
#define DIN_ 2048
#define DSM_ 1280
#define DCAT_ 2560

// ---------------------------------------------------------------------------
// Device scratch (allocation-free: __device__ globals)
// ---------------------------------------------------------------------------
__device__ float g_sf [(size_t)BT_ * S_];      // sfeats fp32 (for zs)
__device__ float g_gl [(size_t)BT_ * 4096];    // large pre-gates
__device__ float g_gs [(size_t)BT_ * 2048];    // small pre-gates
__device__ float g_zs [(size_t)BT_ * 2];
__device__ float g_gatesL[B_ * 4096];
__device__ float g_gatesS[B_ * 2048];
__device__ float g_hl[B_ * L_];
__device__ float g_cl[B_ * L_];
__device__ float g_hs[B_ * S_];
__device__ float g_cs[B_ * S_];
__device__ int   g_r[B_];

// bf16 split operands
__device__ __nv_bfloat16 g_xhi [(size_t)BT_ * DIN_];
__device__ __nv_bfloat16 g_xlo [(size_t)BT_ * DIN_];
__device__ __nv_bfloat16 g_xshi[(size_t)BT_ * DSM_];
__device__ __nv_bfloat16 g_xslo[(size_t)BT_ * DSM_];
__device__ __nv_bfloat16 g_cathi[(size_t)BT_ * DCAT_];
__device__ __nv_bfloat16 g_catlo[(size_t)BT_ * DCAT_];
__device__ __nv_bfloat16 g_wphi[(size_t)2048 * 2048];
__device__ __nv_bfloat16 g_wplo[(size_t)2048 * 2048];
__device__ __nv_bfloat16 g_wshi[(size_t)512 * 1280];
__device__ __nv_bfloat16 g_wslo[(size_t)512 * 1280];
__device__ __nv_bfloat16 g_wlhi[(size_t)4096 * 2560];
__device__ __nv_bfloat16 g_wllo[(size_t)4096 * 2560];
__device__ __nv_bfloat16 g_wsihi[(size_t)2048 * 512];
__device__ __nv_bfloat16 g_wsilo[(size_t)2048 * 512];

#define EPI_BNRELU 1
#define EPI_PRE    2
#define EPI_BIAS2  3

// ---------------------------------------------------------------------------
// PTX helpers (all valid on .target sm_100)
// ---------------------------------------------------------------------------
__device__ __forceinline__ uint32_t smem_u32(const void* p) {
    uint32_t a;
    asm("{ .reg .u64 t; cvta.to.shared.u64 t, %1; cvt.u32.u64 %0, t; }"
        : "=r"(a) : "l"(p));
    return a;
}
__device__ __forceinline__ void cp16(uint32_t dst, const void* src) {
    size_t g = __cvta_generic_to_global(src);
    asm volatile("cp.async.cg.shared.global [%0], [%1], 16;"
                 :: "r"(dst), "l"(g) : "memory");
}
__device__ __forceinline__ void cp_commit() {
    asm volatile("cp.async.commit_group;" ::: "memory");
}
template <int N> __device__ __forceinline__ void cp_wait() {
    asm volatile("cp.async.wait_group %0;" :: "n"(N) : "memory");
}
__device__ __forceinline__ void ldsm_x4(uint32_t& r0, uint32_t& r1,
                                        uint32_t& r2, uint32_t& r3, uint32_t addr) {
    asm volatile("ldmatrix.sync.aligned.m8n8.x4.shared.b16 {%0,%1,%2,%3}, [%4];"
                 : "=r"(r0), "=r"(r1), "=r"(r2), "=r"(r3) : "r"(addr));
}
__device__ __forceinline__ void mma16816(float* c,
                                         uint32_t a0, uint32_t a1, uint32_t a2, uint32_t a3,
                                         uint32_t b0, uint32_t b1) {
    asm volatile(
        "mma.sync.aligned.m16n8k16.row.col.f32.bf16.bf16.f32 "
        "{%0,%1,%2,%3}, {%4,%5,%6,%7}, {%8,%9}, {%0,%1,%2,%3};"
        : "+f"(c[0]), "+f"(c[1]), "+f"(c[2]), "+f"(c[3])
        : "r"(a0), "r"(a1), "r"(a2), "r"(a3), "r"(b0), "r"(b1));
}

// ===========================================================================
// Tensor-core split-bf16 GEMM:  C[M,N] = A[M,K] @ W[N,K]^T (fp32-ish)
// Ahi.Bhi + Ahi.Blo + Alo.Bhi accumulated fp32 in registers.
// CTA: 256 threads (8 warps), tile 128x128, BK=64 bf16, 3-stage cp.async.
// Warp grid 2x4: each warp computes 64x32 via 4x4 m16n8k16 fragments.
// ===========================================================================
#define STAGE_BYTES 32768            // A 16KB + B 16KB
#define TC_SMEM (3 * STAGE_BYTES)

template <int EPI>
__global__ void __launch_bounds__(256, 1)
gemm_mma128(const __nv_bfloat16* __restrict__ Ahi, const __nv_bfloat16* __restrict__ Alo, int lda,
            const __nv_bfloat16* __restrict__ Bhi, const __nv_bfloat16* __restrict__ Blo,
            int K,
            float* __restrict__ C, int ldc,
            __nv_bfloat16* __restrict__ Chi, __nv_bfloat16* __restrict__ Clo, int ldch,
            const float* __restrict__ p0, const float* __restrict__ p1,
            const float* __restrict__ p2)
{
    extern __shared__ char smem[];
    const uint32_t sb = smem_u32(smem);
    const int tid  = threadIdx.x;
    const int wid  = tid >> 5, lane = tid & 31;
    const int wm   = wid & 1,  wn   = wid >> 1;       // 2x4 warp grid
    const int m0   = blockIdx.y * 128, n0 = blockIdx.x * 128;

    // ---- cp.async load plan: 4 chunks A + 4 chunks B per thread per slab ----
    // id = j*256 + tid, r = id>>3 (0..127), c = id&7; sw chunk = c ^ (r&7)
    const int nkA = K >> 6;          // 64-elem slabs per segment
    const int NS  = 3 * nkA;         // (hi,hi) (hi,lo) (lo,hi)
    const __nv_bfloat16* Aseg[3] = { Ahi, Ahi, Alo };
    const __nv_bfloat16* Bseg[3] = { Bhi, Blo, Bhi };

    auto load_slab = [&](int s, int buf) {
        int seg = s / nkA;
        int k0  = (s - seg * nkA) << 6;
        const __nv_bfloat16* A  = Aseg[seg];
        const __nv_bfloat16* Bp = Bseg[seg];
        uint32_t ab = sb + (uint32_t)buf * STAGE_BYTES;
        uint32_t bb = ab + 16384u;
#pragma unroll
        for (int j = 0; j < 4; ++j) {
            int id = j * 256 + tid;
            int r  = id >> 3;
            int c  = id & 7;
            uint32_t sw = (uint32_t)(r * 128 + ((c ^ (r & 7)) << 4));
            cp16(ab + sw, A  + (size_t)(m0 + r) * lda + k0 + c * 8);
            cp16(bb + sw, Bp + (size_t)(n0 + r) * K   + k0 + c * 8);
        }
        cp_commit();
    };

    // ---- per-lane ldmatrix address components ----
    const int lrow = ((lane >> 3) & 1) * 8 + (lane & 7);  // row-within-16 tile
    const int lhi  = lane >> 4;                           // k-chunk half select
    const int llo7 = lane & 7;
    // rowTerm[mt]: byte offset of logical row (A: wm*64 + mt*16 + lrow)
    uint32_t rowTermA[4], rowTermB[2];
#pragma unroll
    for (int mt = 0; mt < 4; ++mt) rowTermA[mt] = (uint32_t)((wm * 64 + mt * 16 + lrow) * 128);
#pragma unroll
    for (int nt2 = 0; nt2 < 2; ++nt2) rowTermB[nt2] = (uint32_t)((wn * 32 + nt2 * 16 + lrow) * 128);
    uint32_t chunkXor[4];
#pragma unroll
    for (int kk = 0; kk < 4; ++kk) chunkXor[kk] = (uint32_t)(((2 * kk + lhi) ^ llo7) << 4);

    float acc[4][4][4];
#pragma unroll
    for (int i = 0; i < 4; ++i)
#pragma unroll
        for (int j = 0; j < 4; ++j)
#pragma unroll
            for (int q = 0; q < 4; ++q) acc[i][j][q] = 0.0f;

    load_slab(0, 0);
    load_slab(1, 1);

    for (int s = 0; s < NS; ++s) {
        if (s + 1 < NS) cp_wait<1>(); else cp_wait<0>();
        __syncthreads();
        if (s + 2 < NS) load_slab(s + 2, (s + 2) % 3);

        const uint32_t ab = sb + (uint32_t)(s % 3) * STAGE_BYTES;
        const uint32_t bb = ab + 16384u;
#pragma unroll
        for (int kk = 0; kk < 4; ++kk) {
            uint32_t a[4][4];
#pragma unroll
            for (int mt = 0; mt < 4; ++mt)
                ldsm_x4(a[mt][0], a[mt][1], a[mt][2], a[mt][3],
                        ab + rowTermA[mt] + chunkXor[kk]);
            uint32_t bf[4][2];
#pragma unroll
            for (int nt2 = 0; nt2 < 2; ++nt2) {
                uint32_t r0, r1, r2, r3;
                ldsm_x4(r0, r1, r2, r3, bb + rowTermB[nt2] + chunkXor[kk]);
                bf[nt2 * 2 + 0][0] = r0; bf[nt2 * 2 + 0][1] = r2;
                bf[nt2 * 2 + 1][0] = r1; bf[nt2 * 2 + 1][1] = r3;
            }
#pragma unroll
            for (int mt = 0; mt < 4; ++mt)
#pragma unroll
                for (int nt = 0; nt < 4; ++nt)
                    mma16816(acc[mt][nt], a[mt][0], a[mt][1], a[mt][2], a[mt][3],
                             bf[nt][0], bf[nt][1]);
        }
        __syncthreads();
    }

    // ---- epilogue: mma fragment layout -> global ----
    const float bnm = rsqrtf(1.0f + 1e-5f);
    const int mwarp = m0 + wm * 64;
    const int nwarp = n0 + wn * 32;
#pragma unroll
    for (int mt = 0; mt < 4; ++mt) {
#pragma unroll
        for (int nt = 0; nt < 4; ++nt) {
#pragma unroll
            for (int half = 0; half < 2; ++half) {
                const int m = mwarp + mt * 16 + (lane >> 2) + half * 8;
                const int n = nwarp + nt * 8 + (lane & 3) * 2;
                float v0 = acc[mt][nt][half * 2 + 0];
                float v1 = acc[mt][nt][half * 2 + 1];
                if (EPI == EPI_BIAS2) {
                    v0 += p0[n] + p1[n];
                    v1 += p0[n + 1] + p1[n + 1];
                }
                if (EPI == EPI_BNRELU) {
                    v0 = fmaxf((v0 + p0[n])     * (p1[n]     * bnm) + p2[n],     0.0f);
                    v1 = fmaxf((v1 + p0[n + 1]) * (p1[n + 1] * bnm) + p2[n + 1], 0.0f);
                }
                if (C) {
                    float2 f2; f2.x = v0; f2.y = v1;
                    *(float2*)(C + (size_t)m * ldc + n) = f2;
                }
                if (Chi) {
                    __nv_bfloat16 h0 = __float2bfloat16(v0);
                    __nv_bfloat16 h1 = __float2bfloat16(v1);
                    __nv_bfloat16 l0 = __float2bfloat16(v0 - __bfloat162float(h0));
                    __nv_bfloat16 l1 = __float2bfloat16(v1 - __bfloat162float(h1));
                    __nv_bfloat162 hh; hh.x = h0; hh.y = h1;
                    __nv_bfloat162 ll; ll.x = l0; ll.y = l1;
                    *(__nv_bfloat162*)(Chi + (size_t)m * ldch + n) = hh;
                    *(__nv_bfloat162*)(Clo + (size_t)m * ldch + n) = ll;
                }
            }
        }
    }
}

// ---------------------------------------------------------------------------
// fp32 -> (hi, lo) bf16 split, vectorized by 4
// ---------------------------------------------------------------------------
__global__ void splitf_kernel(const float* __restrict__ src,
                              __nv_bfloat16* __restrict__ hi,
                              __nv_bfloat16* __restrict__ lo, int n4)
{
    int i = blockIdx.x * blockDim.x + threadIdx.x;
    if (i >= n4) return;
    float4 v = ((const float4*)src)[i];
    __nv_bfloat16 h0 = __float2bfloat16(v.x), h1 = __float2bfloat16(v.y);
    __nv_bfloat16 h2 = __float2bfloat16(v.z), h3 = __float2bfloat16(v.w);
    __nv_bfloat16 l0 = __float2bfloat16(v.x - __bfloat162float(h0));
    __nv_bfloat16 l1 = __float2bfloat16(v.y - __bfloat162float(h1));
    __nv_bfloat16 l2 = __float2bfloat16(v.z - __bfloat162float(h2));
    __nv_bfloat16 l3 = __float2bfloat16(v.w - __bfloat162float(h3));
    __nv_bfloat162 hA; hA.x = h0; hA.y = h1;
    __nv_bfloat162 hB; hB.x = h2; hB.y = h3;
    __nv_bfloat162 lA; lA.x = l0; lA.y = l1;
    __nv_bfloat162 lB; lB.x = l2; lB.y = l3;
    ((__nv_bfloat162*)hi)[2 * i]     = hA;
    ((__nv_bfloat162*)hi)[2 * i + 1] = hB;
    ((__nv_bfloat162*)lo)[2 * i]     = lA;
    ((__nv_bfloat162*)lo)[2 * i + 1] = lB;
}

// ===========================================================================
// Phase-2 GEMM (small M): 128x64 tile, BK=16, 256 threads, 8x4/thread
// ===========================================================================
template <int EPI>
__global__ void __launch_bounds__(256)
gemm128x64(const float* __restrict__ A, int lda,
           const float* __restrict__ W, int K,
           float* __restrict__ C, int ldc,
           const float* __restrict__ p0, int ldp)
{
    __shared__ float As[16][128];
    __shared__ float Bs[16][64];

    const int tid = threadIdx.x;
    const int m0  = blockIdx.y * 128;
    const int n0  = blockIdx.x * 64;
    const int tx  = tid & 15;
    const int ty  = tid >> 4;

    float acc[8][4];
#pragma unroll
    for (int i = 0; i < 8; ++i)
#pragma unroll
        for (int j = 0; j < 4; ++j) acc[i][j] = 0.0f;

    for (int k0 = 0; k0 < K; k0 += 16) {
#pragma unroll
        for (int u = 0; u < 2; ++u) {
            int li = tid * 2 + u;
            int r  = li >> 2;
            int kc = (li & 3) << 2;
            float4 v = *(const float4*)(A + (size_t)(m0 + r) * lda + k0 + kc);
            As[kc + 0][r] = v.x; As[kc + 1][r] = v.y;
            As[kc + 2][r] = v.z; As[kc + 3][r] = v.w;
        }
        {
            int r  = tid >> 2;
            int kc = (tid & 3) << 2;
            float4 v = *(const float4*)(W + (size_t)(n0 + r) * K + k0 + kc);
            Bs[kc + 0][r] = v.x; Bs[kc + 1][r] = v.y;
            Bs[kc + 2][r] = v.z; Bs[kc + 3][r] = v.w;
        }
        __syncthreads();

#pragma unroll
        for (int k = 0; k < 16; ++k) {
            float rm[8], rn[4];
#pragma unroll
            for (int i = 0; i < 8; ++i) rm[i] = As[k][ty * 8 + i];
#pragma unroll
            for (int j = 0; j < 4; ++j) rn[j] = Bs[k][tx * 4 + j];
#pragma unroll
            for (int i = 0; i < 8; ++i)
#pragma unroll
                for (int j = 0; j < 4; ++j)
                    acc[i][j] = fmaf(rm[i], rn[j], acc[i][j]);
        }
        __syncthreads();
    }

#pragma unroll
    for (int i = 0; i < 8; ++i) {
        int m = m0 + ty * 8 + i;
#pragma unroll
        for (int j = 0; j < 4; ++j) {
            int n = n0 + tx * 4 + j;
            float v = acc[i][j];
            if (EPI == EPI_PRE) v += p0[(size_t)m * ldp + n];
            C[(size_t)m * ldc + n] = v;
        }
    }
}

// ---------------------------------------------------------------------------
__global__ void init_states()
{
    int idx = blockIdx.x * blockDim.x + threadIdx.x;
    if (idx < B_ * L_) { g_hl[idx] = 0.0f; g_cl[idx] = 0.0f; }
    if (idx < B_ * S_) { g_hs[idx] = 0.0f; g_cs[idx] = 0.0f; }
}

__global__ void zs_kernel(const float* __restrict__ Wg, const float* __restrict__ bg)
{
    __shared__ float red0[128], red1[128];
    int m = blockIdx.x;
    const float* s = g_sf + (size_t)m * S_;
    float a0 = 0.0f, a1 = 0.0f;
    for (int k = threadIdx.x; k < S_; k += 128) {
        float sv = s[k];
        a0 = fmaf(sv, Wg[k], a0);
        a1 = fmaf(sv, Wg[DCAT_ + k], a1);
    }
    red0[threadIdx.x] = a0; red1[threadIdx.x] = a1;
    __syncthreads();
    for (int st = 64; st > 0; st >>= 1) {
        if (threadIdx.x < st) {
            red0[threadIdx.x] += red0[threadIdx.x + st];
            red1[threadIdx.x] += red1[threadIdx.x + st];
        }
        __syncthreads();
    }
    if (threadIdx.x == 0) {
        g_zs[2 * m + 0] = red0[0] + bg[0];
        g_zs[2 * m + 1] = red1[0] + bg[1];
    }
}

__global__ void gate_kernel(const float* __restrict__ Wg, int t,
                            float* __restrict__ out_r)
{
    __shared__ float red0[128], red1[128];
    int b = blockIdx.x;
    const float* hl = g_hl + b * L_;
    const float* cl = g_cl + b * L_;
    const float* w0 = Wg + 512;
    const float* w1 = Wg + DCAT_ + 512;
    float a0 = 0.0f, a1 = 0.0f;
    for (int k = threadIdx.x; k < L_; k += 128) {
        float hv = hl[k], cv = cl[k];
        a0 = fmaf(hv, w0[k], a0); a0 = fmaf(cv, w0[L_ + k], a0);
        a1 = fmaf(hv, w1[k], a1); a1 = fmaf(cv, w1[L_ + k], a1);
    }
    red0[threadIdx.x] = a0; red1[threadIdx.x] = a1;
    __syncthreads();
    for (int st = 64; st > 0; st >>= 1) {
        if (threadIdx.x < st) {
            red0[threadIdx.x] += red0[threadIdx.x + st];
            red1[threadIdx.x] += red1[threadIdx.x + st];
        }
        __syncthreads();
    }
    if (threadIdx.x == 0) {
        float z0 = g_zs[(size_t)(b * T_ + t) * 2 + 0] + red0[0];
        float z1 = g_zs[(size_t)(b * T_ + t) * 2 + 1] + red1[0];
        int r = (z0 >= z1) ? 0 : 1;
        g_r[b] = r;
        out_r[(size_t)t * B_ * 2 + b * 2 + 0] = (r == 0) ? 1.0f : 0.0f;
        out_r[(size_t)t * B_ * 2 + b * 2 + 1] = (r == 1) ? 1.0f : 0.0f;
    }
}

__device__ __forceinline__ float sigf(float x) { return 1.0f / (1.0f + expf(-x)); }

__global__ void lstm_small_pw()
{
    int idx = blockIdx.x * blockDim.x + threadIdx.x;
    int b = idx >> 9, n = idx & (S_ - 1);
    const float* g = g_gatesS + b * 2048;
    float i = sigf(g[n]);
    float f = sigf(g[S_ + n]);
    float gg = tanhf(g[2 * S_ + n]);
    float o = sigf(g[3 * S_ + n]);
    float c2 = f * g_cs[idx] + i * gg;
    g_cs[idx] = c2;
    g_hs[idx] = o * tanhf(c2);
}

__global__ void lstm_large_pw()
{
    int idx = blockIdx.x * blockDim.x + threadIdx.x;
    int b = idx >> 10, n = idx & (L_ - 1);
    const float* g = g_gatesL + b * 4096;
    float i = sigf(g[n]);
    float f = sigf(g[L_ + n]);
    float gg = tanhf(g[2 * L_ + n]);
    float o = sigf(g[3 * L_ + n]);
    float cold = g_cl[idx], hold = g_hl[idx];
    float c2 = f * cold + i * gg;
    float h2 = o * tanhf(c2);
    if (g_r[b] == 0) {
        g_hl[idx] = h2;
        g_cl[idx] = c2;
    } else {
        g_hl[idx] = (n < S_) ? g_hs[b * S_ + n] : hold;
        g_cl[idx] = (n < S_) ? g_cs[b * S_ + n] : cold;
    }
}

__global__ void classifier_kernel(const float* __restrict__ Wc,
                                  const float* __restrict__ bc,
                                  float* __restrict__ out)
{
    __shared__ float sh[L_];
    int b = blockIdx.x;
    for (int k = threadIdx.x; k < L_; k += blockDim.x) sh[k] = g_hl[b * L_ + k];
    __syncthreads();
    int n = threadIdx.x;
    if (n < NC_) {
        float a = bc[n];
        const float* w = Wc + (size_t)n * L_;
        for (int k = 0; k < L_; ++k) a = fmaf(sh[k], w[k], a);
        out[(size_t)b * NC_ + n] = a;
    }
}

// ---------------------------------------------------------------------------
// Host launcher
// ---------------------------------------------------------------------------
extern "C" void kernel_launch(void* const* d_in, const int* in_sizes, int n_in,
                              void* d_out, int out_size)
{
    const float* x     = (const float*)d_in[0];
    const float* xs    = (const float*)d_in[1];
    const float* W_p   = (const float*)d_in[2];
    const float* b_p   = (const float*)d_in[3];
    const float* g_p   = (const float*)d_in[4];
    const float* be_p  = (const float*)d_in[5];
    const float* W_s   = (const float*)d_in[6];
    const float* b_s   = (const float*)d_in[7];
    const float* g_s   = (const float*)d_in[8];
    const float* be_s  = (const float*)d_in[9];
    const float* Wih_l = (const float*)d_in[10];
    const float* Whh_l = (const float*)d_in[11];
    const float* bih_l = (const float*)d_in[12];
    const float* bhh_l = (const float*)d_in[13];
    const float* Wih_s = (const float*)d_in[14];
    const float* Whh_s = (const float*)d_in[15];
    const float* bih_s = (const float*)d_in[16];
    const float* bhh_s = (const float*)d_in[17];
    const float* W_g   = (const float*)d_in[18];
    const float* b_g   = (const float*)d_in[19];
    const float* W_c   = (const float*)d_in[20];
    const float* b_c   = (const float*)d_in[21];

    float* out        = (float*)d_out;
    float* out_logits = out;
    float* out_r      = out + (size_t)B_ * NC_;

    static bool init = false;
    static float *p_sf, *p_gl, *p_gs, *p_gatesL, *p_gatesS, *p_hl, *p_hs;
    static __nv_bfloat16 *p_xhi, *p_xlo, *p_xshi, *p_xslo, *p_cathi, *p_catlo,
        *p_wphi, *p_wplo, *p_wshi, *p_wslo, *p_wlhi, *p_wllo, *p_wsihi, *p_wsilo;
    if (!init) {
        cudaGetSymbolAddress((void**)&p_sf, g_sf);
        cudaGetSymbolAddress((void**)&p_gl, g_gl);
        cudaGetSymbolAddress((void**)&p_gs, g_gs);
        cudaGetSymbolAddress((void**)&p_gatesL, g_gatesL);
        cudaGetSymbolAddress((void**)&p_gatesS, g_gatesS);
        cudaGetSymbolAddress((void**)&p_hl, g_hl);
        cudaGetSymbolAddress((void**)&p_hs, g_hs);
        cudaGetSymbolAddress((void**)&p_xhi, g_xhi);
        cudaGetSymbolAddress((void**)&p_xlo, g_xlo);
        cudaGetSymbolAddress((void**)&p_xshi, g_xshi);
        cudaGetSymbolAddress((void**)&p_xslo, g_xslo);
        cudaGetSymbolAddress((void**)&p_cathi, g_cathi);
        cudaGetSymbolAddress((void**)&p_catlo, g_catlo);
        cudaGetSymbolAddress((void**)&p_wphi, g_wphi);
        cudaGetSymbolAddress((void**)&p_wplo, g_wplo);
        cudaGetSymbolAddress((void**)&p_wshi, g_wshi);
        cudaGetSymbolAddress((void**)&p_wslo, g_wslo);
        cudaGetSymbolAddress((void**)&p_wlhi, g_wlhi);
        cudaGetSymbolAddress((void**)&p_wllo, g_wllo);
        cudaGetSymbolAddress((void**)&p_wsihi, g_wsihi);
        cudaGetSymbolAddress((void**)&p_wsilo, g_wsilo);
        cudaFuncSetAttribute(gemm_mma128<EPI_BNRELU>,
                             cudaFuncAttributeMaxDynamicSharedMemorySize, TC_SMEM);
        cudaFuncSetAttribute(gemm_mma128<EPI_BIAS2>,
                             cudaFuncAttributeMaxDynamicSharedMemorySize, TC_SMEM);
        init = true;
    }

    init_states<<<(B_ * L_ + 255) / 256, 256>>>();

    // ---- split fp32 -> bf16 hi/lo ----
    auto split = [](const float* s, __nv_bfloat16* h, __nv_bfloat16* l, size_t n) {
        int n4 = (int)(n / 4);
        splitf_kernel<<<(n4 + 255) / 256, 256>>>(s, h, l, n4);
    };
    split(x,     p_xhi,  p_xlo,  (size_t)BT_ * DIN_);
    split(xs,    p_xshi, p_xslo, (size_t)BT_ * DSM_);
    split(W_p,   p_wphi, p_wplo, (size_t)2048 * 2048);
    split(W_s,   p_wshi, p_wslo, (size_t)512 * 1280);
    split(Wih_l, p_wlhi, p_wllo, (size_t)4096 * 2560);
    split(Wih_s, p_wsihi, p_wsilo, (size_t)2048 * 512);

    // ---- phase 1: tensor-core split-bf16 GEMMs ----
    gemm_mma128<EPI_BNRELU><<<dim3(DIN_ / 128, BT_ / 128), 256, TC_SMEM>>>(
        p_xhi, p_xlo, DIN_, p_wphi, p_wplo, DIN_,
        nullptr, 0, p_cathi, p_catlo, DCAT_, b_p, g_p, be_p);
    gemm_mma128<EPI_BNRELU><<<dim3(S_ / 128, BT_ / 128), 256, TC_SMEM>>>(
        p_xshi, p_xslo, DSM_, p_wshi, p_wslo, DSM_,
        p_sf, S_, p_cathi + 2048, p_catlo + 2048, DCAT_, b_s, g_s, be_s);
    gemm_mma128<EPI_BIAS2><<<dim3(4096 / 128, BT_ / 128), 256, TC_SMEM>>>(
        p_cathi, p_catlo, DCAT_, p_wlhi, p_wllo, DCAT_,
        p_gl, 4096, nullptr, nullptr, 0, bih_l, bhh_l, nullptr);
    gemm_mma128<EPI_BIAS2><<<dim3(2048 / 128, BT_ / 128), 256, TC_SMEM>>>(
        p_cathi + 2048, p_catlo + 2048, DCAT_, p_wsihi, p_wsilo, S_,
        p_gs, 2048, nullptr, nullptr, 0, bih_s, bhh_s, nullptr);

    zs_kernel<<<BT_, 128>>>(W_g, b_g);

    // ---- phase 2: sequential recurrence (fp32, precision-critical) ----
    for (int t = 0; t < T_; ++t) {
        gemm128x64<EPI_PRE><<<dim3(2048 / 64, B_ / 128), 256>>>(
            p_hs, S_, Whh_s, S_, p_gatesS, 2048,
            p_gs + (size_t)t * 2048, T_ * 2048);
        lstm_small_pw<<<(B_ * S_) / 256, 256>>>();
        gate_kernel<<<B_, 128>>>(W_g, t, out_r);
        gemm128x64<EPI_PRE><<<dim3(4096 / 64, B_ / 128), 256>>>(
            p_hl, L_, Whh_l, L_, p_gatesL, 4096,
            p_gl + (size_t)t * 4096, T_ * 4096);
        lstm_large_pw<<<(B_ * L_) / 256, 256>>>();
    }

    classifier_kernel<<<B_, 256>>>(W_c, b_c, out_logits);
}

// round 8
// speedup vs baseline: 1.5134x; 1.0062x over previous
#include <cuda_runtime.h>
#include <cuda_bf16.h>
#include <math.h>
#include <stdint.h>

// ---------------------------------------------------------------------------
// Problem constants
// ---------------------------------------------------------------------------
#define B_   256
#define T_   64
#define L_   1024
#define S_   512
#define NC_  239
#define BT_  (B_ * T_)          // 16384
#define DIN_ 2048
#define DSM_ 1280
#define DCAT_ 2560

// ---------------------------------------------------------------------------
// Device scratch (allocation-free: __device__ globals)
// ---------------------------------------------------------------------------
__device__ float g_sf [(size_t)BT_ * S_];      // sfeats fp32 (for zs)
__device__ float g_gl [(size_t)BT_ * 4096];    // large pre-gates
__device__ float g_gs [(size_t)BT_ * 2048];    // small pre-gates
__device__ float g_zs [(size_t)BT_ * 2];
__device__ float g_gatesL[B_ * 4096];
__device__ float g_gatesS[B_ * 2048];
__device__ float g_hl[B_ * L_];
__device__ float g_cl[B_ * L_];
__device__ float g_hs[B_ * S_];
__device__ float g_cs[B_ * S_];
__device__ int   g_r[B_];

// bf16 split operands (phase-1 only)
__device__ __nv_bfloat16 g_xhi [(size_t)BT_ * DIN_];
__device__ __nv_bfloat16 g_xlo [(size_t)BT_ * DIN_];
__device__ __nv_bfloat16 g_xshi[(size_t)BT_ * DSM_];
__device__ __nv_bfloat16 g_xslo[(size_t)BT_ * DSM_];
__device__ __nv_bfloat16 g_cathi[(size_t)BT_ * DCAT_];
__device__ __nv_bfloat16 g_catlo[(size_t)BT_ * DCAT_];
__device__ __nv_bfloat16 g_wphi[(size_t)2048 * 2048];
__device__ __nv_bfloat16 g_wplo[(size_t)2048 * 2048];
__device__ __nv_bfloat16 g_wshi[(size_t)512 * 1280];
__device__ __nv_bfloat16 g_wslo[(size_t)512 * 1280];
__device__ __nv_bfloat16 g_wlhi[(size_t)4096 * 2560];
__device__ __nv_bfloat16 g_wllo[(size_t)4096 * 2560];
__device__ __nv_bfloat16 g_wsihi[(size_t)2048 * 512];
__device__ __nv_bfloat16 g_wsilo[(size_t)2048 * 512];

#define EPI_BNRELU 1
#define EPI_BIAS2  3

// ---------------------------------------------------------------------------
// PTX helpers (all valid on .target sm_100)
// ---------------------------------------------------------------------------
__device__ __forceinline__ uint32_t smem_u32(const void* p) {
    uint32_t a;
    asm("{ .reg .u64 t; cvta.to.shared.u64 t, %1; cvt.u32.u64 %0, t; }"
        : "=r"(a) : "l"(p));
    return a;
}
__device__ __forceinline__ void cp16(uint32_t dst, const void* src) {
    size_t g = __cvta_generic_to_global(src);
    asm volatile("cp.async.cg.shared.global [%0], [%1], 16;"
                 :: "r"(dst), "l"(g) : "memory");
}
__device__ __forceinline__ void cp_commit() {
    asm volatile("cp.async.commit_group;" ::: "memory");
}
template <int N> __device__ __forceinline__ void cp_wait() {
    asm volatile("cp.async.wait_group %0;" :: "n"(N) : "memory");
}
__device__ __forceinline__ void ldsm_x4(uint32_t& r0, uint32_t& r1,
                                        uint32_t& r2, uint32_t& r3, uint32_t addr) {
    asm volatile("ldmatrix.sync.aligned.m8n8.x4.shared.b16 {%0,%1,%2,%3}, [%4];"
                 : "=r"(r0), "=r"(r1), "=r"(r2), "=r"(r3) : "r"(addr));
}
__device__ __forceinline__ void mma16816(float* c,
                                         uint32_t a0, uint32_t a1, uint32_t a2, uint32_t a3,
                                         uint32_t b0, uint32_t b1) {
    asm volatile(
        "mma.sync.aligned.m16n8k16.row.col.f32.bf16.bf16.f32 "
        "{%0,%1,%2,%3}, {%4,%5,%6,%7}, {%8,%9}, {%0,%1,%2,%3};"
        : "+f"(c[0]), "+f"(c[1]), "+f"(c[2]), "+f"(c[3])
        : "r"(a0), "r"(a1), "r"(a2), "r"(a3), "r"(b0), "r"(b1));
}

// ===========================================================================
// Phase-1 tensor-core split-bf16 GEMM (identical to R5's passing kernel)
// ===========================================================================
#define STAGE_BYTES 32768            // A 16KB + B 16KB
#define TC_SMEM (3 * STAGE_BYTES)

template <int EPI>
__global__ void __launch_bounds__(256, 1)
gemm_mma128(const __nv_bfloat16* __restrict__ Ahi, const __nv_bfloat16* __restrict__ Alo, int lda,
            const __nv_bfloat16* __restrict__ Bhi, const __nv_bfloat16* __restrict__ Blo,
            int K,
            float* __restrict__ C, int ldc,
            __nv_bfloat16* __restrict__ Chi, __nv_bfloat16* __restrict__ Clo, int ldch,
            const float* __restrict__ p0, const float* __restrict__ p1,
            const float* __restrict__ p2)
{
    extern __shared__ char smem[];
    const uint32_t sb = smem_u32(smem);
    const int tid  = threadIdx.x;
    const int wid  = tid >> 5, lane = tid & 31;
    const int wm   = wid & 1,  wn   = wid >> 1;       // 2x4 warp grid
    const int m0   = blockIdx.y * 128, n0 = blockIdx.x * 128;

    const int nkA = K >> 6;
    const int NS  = 3 * nkA;
    const __nv_bfloat16* Aseg[3] = { Ahi, Ahi, Alo };
    const __nv_bfloat16* Bseg[3] = { Bhi, Blo, Bhi };

    auto load_slab = [&](int s, int buf) {
        int seg = s / nkA;
        int k0  = (s - seg * nkA) << 6;
        const __nv_bfloat16* A  = Aseg[seg];
        const __nv_bfloat16* Bp = Bseg[seg];
        uint32_t ab = sb + (uint32_t)buf * STAGE_BYTES;
        uint32_t bb = ab + 16384u;
#pragma unroll
        for (int j = 0; j < 4; ++j) {
            int id = j * 256 + tid;
            int r  = id >> 3;
            int c  = id & 7;
            uint32_t sw = (uint32_t)(r * 128 + ((c ^ (r & 7)) << 4));
            cp16(ab + sw, A  + (size_t)(m0 + r) * lda + k0 + c * 8);
            cp16(bb + sw, Bp + (size_t)(n0 + r) * K   + k0 + c * 8);
        }
        cp_commit();
    };

    const int lrow = ((lane >> 3) & 1) * 8 + (lane & 7);
    const int lhi  = lane >> 4;
    const int llo7 = lane & 7;
    uint32_t rowTermA[4], rowTermB[2];
#pragma unroll
    for (int mt = 0; mt < 4; ++mt) rowTermA[mt] = (uint32_t)((wm * 64 + mt * 16 + lrow) * 128);
#pragma unroll
    for (int nt2 = 0; nt2 < 2; ++nt2) rowTermB[nt2] = (uint32_t)((wn * 32 + nt2 * 16 + lrow) * 128);
    uint32_t chunkXor[4];
#pragma unroll
    for (int kk = 0; kk < 4; ++kk) chunkXor[kk] = (uint32_t)(((2 * kk + lhi) ^ llo7) << 4);

    float acc[4][4][4];
#pragma unroll
    for (int i = 0; i < 4; ++i)
#pragma unroll
        for (int j = 0; j < 4; ++j)
#pragma unroll
            for (int q = 0; q < 4; ++q) acc[i][j][q] = 0.0f;

    load_slab(0, 0);
    load_slab(1, 1);

    for (int s = 0; s < NS; ++s) {
        if (s + 1 < NS) cp_wait<1>(); else cp_wait<0>();
        __syncthreads();
        if (s + 2 < NS) load_slab(s + 2, (s + 2) % 3);

        const uint32_t ab = sb + (uint32_t)(s % 3) * STAGE_BYTES;
        const uint32_t bb = ab + 16384u;
#pragma unroll
        for (int kk = 0; kk < 4; ++kk) {
            uint32_t a[4][4];
#pragma unroll
            for (int mt = 0; mt < 4; ++mt)
                ldsm_x4(a[mt][0], a[mt][1], a[mt][2], a[mt][3],
                        ab + rowTermA[mt] + chunkXor[kk]);
            uint32_t bf[4][2];
#pragma unroll
            for (int nt2 = 0; nt2 < 2; ++nt2) {
                uint32_t r0, r1, r2, r3;
                ldsm_x4(r0, r1, r2, r3, bb + rowTermB[nt2] + chunkXor[kk]);
                bf[nt2 * 2 + 0][0] = r0; bf[nt2 * 2 + 0][1] = r2;
                bf[nt2 * 2 + 1][0] = r1; bf[nt2 * 2 + 1][1] = r3;
            }
#pragma unroll
            for (int mt = 0; mt < 4; ++mt)
#pragma unroll
                for (int nt = 0; nt < 4; ++nt)
                    mma16816(acc[mt][nt], a[mt][0], a[mt][1], a[mt][2], a[mt][3],
                             bf[nt][0], bf[nt][1]);
        }
        __syncthreads();
    }

    const float bnm = rsqrtf(1.0f + 1e-5f);
    const int mwarp = m0 + wm * 64;
    const int nwarp = n0 + wn * 32;
#pragma unroll
    for (int mt = 0; mt < 4; ++mt) {
#pragma unroll
        for (int nt = 0; nt < 4; ++nt) {
#pragma unroll
            for (int half = 0; half < 2; ++half) {
                const int m = mwarp + mt * 16 + (lane >> 2) + half * 8;
                const int n = nwarp + nt * 8 + (lane & 3) * 2;
                float v0 = acc[mt][nt][half * 2 + 0];
                float v1 = acc[mt][nt][half * 2 + 1];
                if (EPI == EPI_BIAS2) {
                    v0 += p0[n] + p1[n];
                    v1 += p0[n + 1] + p1[n + 1];
                }
                if (EPI == EPI_BNRELU) {
                    v0 = fmaxf((v0 + p0[n])     * (p1[n]     * bnm) + p2[n],     0.0f);
                    v1 = fmaxf((v1 + p0[n + 1]) * (p1[n + 1] * bnm) + p2[n + 1], 0.0f);
                }
                if (C) {
                    float2 f2; f2.x = v0; f2.y = v1;
                    *(float2*)(C + (size_t)m * ldc + n) = f2;
                }
                if (Chi) {
                    __nv_bfloat16 h0 = __float2bfloat16(v0);
                    __nv_bfloat16 h1 = __float2bfloat16(v1);
                    __nv_bfloat16 l0 = __float2bfloat16(v0 - __bfloat162float(h0));
                    __nv_bfloat16 l1 = __float2bfloat16(v1 - __bfloat162float(h1));
                    __nv_bfloat162 hh; hh.x = h0; hh.y = h1;
                    __nv_bfloat162 ll; ll.x = l0; ll.y = l1;
                    *(__nv_bfloat162*)(Chi + (size_t)m * ldch + n) = hh;
                    *(__nv_bfloat162*)(Clo + (size_t)m * ldch + n) = ll;
                }
            }
        }
    }
}

// ---------------------------------------------------------------------------
// fp32 -> (hi, lo) bf16 split, vectorized by 4
// ---------------------------------------------------------------------------
__global__ void splitf_kernel(const float* __restrict__ src,
                              __nv_bfloat16* __restrict__ hi,
                              __nv_bfloat16* __restrict__ lo, int n4)
{
    int i = blockIdx.x * blockDim.x + threadIdx.x;
    if (i >= n4) return;
    float4 v = ((const float4*)src)[i];
    __nv_bfloat16 h0 = __float2bfloat16(v.x), h1 = __float2bfloat16(v.y);
    __nv_bfloat16 h2 = __float2bfloat16(v.z), h3 = __float2bfloat16(v.w);
    __nv_bfloat16 l0 = __float2bfloat16(v.x - __bfloat162float(h0));
    __nv_bfloat16 l1 = __float2bfloat16(v.y - __bfloat162float(h1));
    __nv_bfloat16 l2 = __float2bfloat16(v.z - __bfloat162float(h2));
    __nv_bfloat16 l3 = __float2bfloat16(v.w - __bfloat162float(h3));
    __nv_bfloat162 hA; hA.x = h0; hA.y = h1;
    __nv_bfloat162 hB; hB.x = h2; hB.y = h3;
    __nv_bfloat162 lA; lA.x = l0; lA.y = l1;
    __nv_bfloat162 lB; lB.x = l2; lB.y = l3;
    ((__nv_bfloat162*)hi)[2 * i]     = hA;
    ((__nv_bfloat162*)hi)[2 * i + 1] = hB;
    ((__nv_bfloat162*)lo)[2 * i]     = lA;
    ((__nv_bfloat162*)lo)[2 * i + 1] = lB;
}

// ===========================================================================
// Phase-2 fp32 GEMM body (proven R1-R5): 128x64 tile, BK=16, 256 thr, 8x4
// ===========================================================================
__device__ __forceinline__ void
gemm64_body(int m0, int n0,
            const float* __restrict__ A, int lda,
            const float* __restrict__ W, int K,
            float* __restrict__ C, int ldc,
            const float* __restrict__ p0, int ldp)
{
    __shared__ float As[16][128];
    __shared__ float Bs[16][64];

    const int tid = threadIdx.x;
    const int tx  = tid & 15;
    const int ty  = tid >> 4;

    float acc[8][4];
#pragma unroll
    for (int i = 0; i < 8; ++i)
#pragma unroll
        for (int j = 0; j < 4; ++j) acc[i][j] = 0.0f;

    for (int k0 = 0; k0 < K; k0 += 16) {
#pragma unroll
        for (int u = 0; u < 2; ++u) {
            int li = tid * 2 + u;
            int r  = li >> 2;
            int kc = (li & 3) << 2;
            float4 v = *(const float4*)(A + (size_t)(m0 + r) * lda + k0 + kc);
            As[kc + 0][r] = v.x; As[kc + 1][r] = v.y;
            As[kc + 2][r] = v.z; As[kc + 3][r] = v.w;
        }
        {
            int r  = tid >> 2;
            int kc = (tid & 3) << 2;
            float4 v = *(const float4*)(W + (size_t)(n0 + r) * K + k0 + kc);
            Bs[kc + 0][r] = v.x; Bs[kc + 1][r] = v.y;
            Bs[kc + 2][r] = v.z; Bs[kc + 3][r] = v.w;
        }
        __syncthreads();

#pragma unroll
        for (int k = 0; k < 16; ++k) {
            float rm[8], rn[4];
#pragma unroll
            for (int i = 0; i < 8; ++i) rm[i] = As[k][ty * 8 + i];
#pragma unroll
            for (int j = 0; j < 4; ++j) rn[j] = Bs[k][tx * 4 + j];
#pragma unroll
            for (int i = 0; i < 8; ++i)
#pragma unroll
                for (int j = 0; j < 4; ++j)
                    acc[i][j] = fmaf(rm[i], rn[j], acc[i][j]);
        }
        __syncthreads();
    }

#pragma unroll
    for (int i = 0; i < 8; ++i) {
        int m = m0 + ty * 8 + i;
#pragma unroll
        for (int j = 0; j < 4; ++j) {
            int n = n0 + tx * 4 + j;
            C[(size_t)m * ldc + n] = acc[i][j] + p0[(size_t)m * ldp + n];
        }
    }
}

// Fused phase-2 recurrent GEMM: blocks x<64 -> large, x>=64 -> small.
__global__ void __launch_bounds__(256)
gemm_p2_fused(const float* __restrict__ hl, const float* __restrict__ hs,
              const float* __restrict__ Wl, const float* __restrict__ Ws,
              float* __restrict__ gatesL, float* __restrict__ gatesS,
              const float* __restrict__ pgl, const float* __restrict__ pgs,
              int t)
{
    const int bx = blockIdx.x;
    const int m0 = blockIdx.y * 128;
    const float *A, *W, *p0;
    float* C;
    int lda, K, ldc, ldp, n0;
    if (bx < 64) {
        A = hl; lda = L_; W = Wl; K = L_;
        C = gatesL; ldc = 4096;
        p0 = pgl + (size_t)t * 4096; ldp = T_ * 4096;
        n0 = bx * 64;
    } else {
        A = hs; lda = S_; W = Ws; K = S_;
        C = gatesS; ldc = 2048;
        p0 = pgs + (size_t)t * 2048; ldp = T_ * 2048;
        n0 = (bx - 64) * 64;
    }
    gemm64_body(m0, n0, A, lda, W, K, C, ldc, p0, ldp);
}

// ---------------------------------------------------------------------------
__global__ void init_states()
{
    int idx = blockIdx.x * blockDim.x + threadIdx.x;
    if (idx < B_ * L_) { g_hl[idx] = 0.0f; g_cl[idx] = 0.0f; }
    if (idx < B_ * S_) { g_hs[idx] = 0.0f; g_cs[idx] = 0.0f; }
}

__global__ void zs_kernel(const float* __restrict__ Wg, const float* __restrict__ bg)
{
    __shared__ float red0[128], red1[128];
    int m = blockIdx.x;
    const float* s = g_sf + (size_t)m * S_;
    float a0 = 0.0f, a1 = 0.0f;
    for (int k = threadIdx.x; k < S_; k += 128) {
        float sv = s[k];
        a0 = fmaf(sv, Wg[k], a0);
        a1 = fmaf(sv, Wg[DCAT_ + k], a1);
    }
    red0[threadIdx.x] = a0; red1[threadIdx.x] = a1;
    __syncthreads();
    for (int st = 64; st > 0; st >>= 1) {
        if (threadIdx.x < st) {
            red0[threadIdx.x] += red0[threadIdx.x + st];
            red1[threadIdx.x] += red1[threadIdx.x + st];
        }
        __syncthreads();
    }
    if (threadIdx.x == 0) {
        g_zs[2 * m + 0] = red0[0] + bg[0];
        g_zs[2 * m + 1] = red1[0] + bg[1];
    }
}

__device__ __forceinline__ float sigf(float x) { return 1.0f / (1.0f + expf(-x)); }

// ---------------------------------------------------------------------------
// Fused: blocks [0,512) small-cell pointwise; blocks [512,768) gate argmax
// ---------------------------------------------------------------------------
__global__ void pw_small_gate(const float* __restrict__ Wg, int t,
                              float* __restrict__ out_r)
{
    if (blockIdx.x < 512) {
        int idx = blockIdx.x * 256 + threadIdx.x;          // B_*S_ = 131072
        int b = idx >> 9, n = idx & (S_ - 1);
        const float* g = g_gatesS + b * 2048;
        float i = sigf(g[n]);
        float f = sigf(g[S_ + n]);
        float gg = tanhf(g[2 * S_ + n]);
        float o = sigf(g[3 * S_ + n]);
        float c2 = f * g_cs[idx] + i * gg;
        g_cs[idx] = c2;
        g_hs[idx] = o * tanhf(c2);
    } else {
        __shared__ float red0[256], red1[256];
        int b = blockIdx.x - 512;
        const float* hl = g_hl + b * L_;
        const float* cl = g_cl + b * L_;
        const float* w0 = Wg + 512;
        const float* w1 = Wg + DCAT_ + 512;
        float a0 = 0.0f, a1 = 0.0f;
        for (int k = threadIdx.x; k < L_; k += 256) {
            float hv = hl[k], cv = cl[k];
            a0 = fmaf(hv, w0[k], a0); a0 = fmaf(cv, w0[L_ + k], a0);
            a1 = fmaf(hv, w1[k], a1); a1 = fmaf(cv, w1[L_ + k], a1);
        }
        red0[threadIdx.x] = a0; red1[threadIdx.x] = a1;
        __syncthreads();
        for (int st = 128; st > 0; st >>= 1) {
            if (threadIdx.x < st) {
                red0[threadIdx.x] += red0[threadIdx.x + st];
                red1[threadIdx.x] += red1[threadIdx.x + st];
            }
            __syncthreads();
        }
        if (threadIdx.x == 0) {
            float z0 = g_zs[(size_t)(b * T_ + t) * 2 + 0] + red0[0];
            float z1 = g_zs[(size_t)(b * T_ + t) * 2 + 1] + red1[0];
            int r = (z0 >= z1) ? 0 : 1;
            g_r[b] = r;
            out_r[(size_t)t * B_ * 2 + b * 2 + 0] = (r == 0) ? 1.0f : 0.0f;
            out_r[(size_t)t * B_ * 2 + b * 2 + 1] = (r == 1) ? 1.0f : 0.0f;
        }
    }
}

__global__ void lstm_large_pw()
{
    int idx = blockIdx.x * blockDim.x + threadIdx.x;
    int b = idx >> 10, n = idx & (L_ - 1);
    const float* g = g_gatesL + b * 4096;
    float i = sigf(g[n]);
    float f = sigf(g[L_ + n]);
    float gg = tanhf(g[2 * L_ + n]);
    float o = sigf(g[3 * L_ + n]);
    float cold = g_cl[idx], hold = g_hl[idx];
    float c2 = f * cold + i * gg;
    float h2 = o * tanhf(c2);
    if (g_r[b] == 0) {
        g_hl[idx] = h2;
        g_cl[idx] = c2;
    } else {
        g_hl[idx] = (n < S_) ? g_hs[b * S_ + n] : hold;
        g_cl[idx] = (n < S_) ? g_cs[b * S_ + n] : cold;
    }
}

__global__ void classifier_kernel(const float* __restrict__ Wc,
                                  const float* __restrict__ bc,
                                  float* __restrict__ out)
{
    __shared__ float sh[L_];
    int b = blockIdx.x;
    for (int k = threadIdx.x; k < L_; k += blockDim.x) sh[k] = g_hl[b * L_ + k];
    __syncthreads();
    int n = threadIdx.x;
    if (n < NC_) {
        float a = bc[n];
        const float* w = Wc + (size_t)n * L_;
        for (int k = 0; k < L_; ++k) a = fmaf(sh[k], w[k], a);
        out[(size_t)b * NC_ + n] = a;
    }
}

// ---------------------------------------------------------------------------
// Host launcher
// ---------------------------------------------------------------------------
extern "C" void kernel_launch(void* const* d_in, const int* in_sizes, int n_in,
                              void* d_out, int out_size)
{
    const float* x     = (const float*)d_in[0];
    const float* xs    = (const float*)d_in[1];
    const float* W_p   = (const float*)d_in[2];
    const float* b_p   = (const float*)d_in[3];
    const float* g_p   = (const float*)d_in[4];
    const float* be_p  = (const float*)d_in[5];
    const float* W_s   = (const float*)d_in[6];
    const float* b_s   = (const float*)d_in[7];
    const float* g_s   = (const float*)d_in[8];
    const float* be_s  = (const float*)d_in[9];
    const float* Wih_l = (const float*)d_in[10];
    const float* Whh_l = (const float*)d_in[11];
    const float* bih_l = (const float*)d_in[12];
    const float* bhh_l = (const float*)d_in[13];
    const float* Wih_s = (const float*)d_in[14];
    const float* Whh_s = (const float*)d_in[15];
    const float* bih_s = (const float*)d_in[16];
    const float* bhh_s = (const float*)d_in[17];
    const float* W_g   = (const float*)d_in[18];
    const float* b_g   = (const float*)d_in[19];
    const float* W_c   = (const float*)d_in[20];
    const float* b_c   = (const float*)d_in[21];

    float* out        = (float*)d_out;
    float* out_logits = out;
    float* out_r      = out + (size_t)B_ * NC_;

    static bool init = false;
    static float *p_sf, *p_gl, *p_gs, *p_gatesL, *p_gatesS, *p_hl, *p_hs;
    static __nv_bfloat16 *p_xhi, *p_xlo, *p_xshi, *p_xslo, *p_cathi, *p_catlo,
        *p_wphi, *p_wplo, *p_wshi, *p_wslo, *p_wlhi, *p_wllo, *p_wsihi, *p_wsilo;
    if (!init) {
        cudaGetSymbolAddress((void**)&p_sf, g_sf);
        cudaGetSymbolAddress((void**)&p_gl, g_gl);
        cudaGetSymbolAddress((void**)&p_gs, g_gs);
        cudaGetSymbolAddress((void**)&p_gatesL, g_gatesL);
        cudaGetSymbolAddress((void**)&p_gatesS, g_gatesS);
        cudaGetSymbolAddress((void**)&p_hl, g_hl);
        cudaGetSymbolAddress((void**)&p_hs, g_hs);
        cudaGetSymbolAddress((void**)&p_xhi, g_xhi);
        cudaGetSymbolAddress((void**)&p_xlo, g_xlo);
        cudaGetSymbolAddress((void**)&p_xshi, g_xshi);
        cudaGetSymbolAddress((void**)&p_xslo, g_xslo);
        cudaGetSymbolAddress((void**)&p_cathi, g_cathi);
        cudaGetSymbolAddress((void**)&p_catlo, g_catlo);
        cudaGetSymbolAddress((void**)&p_wphi, g_wphi);
        cudaGetSymbolAddress((void**)&p_wplo, g_wplo);
        cudaGetSymbolAddress((void**)&p_wshi, g_wshi);
        cudaGetSymbolAddress((void**)&p_wslo, g_wslo);
        cudaGetSymbolAddress((void**)&p_wlhi, g_wlhi);
        cudaGetSymbolAddress((void**)&p_wllo, g_wllo);
        cudaGetSymbolAddress((void**)&p_wsihi, g_wsihi);
        cudaGetSymbolAddress((void**)&p_wsilo, g_wsilo);
        cudaFuncSetAttribute(gemm_mma128<EPI_BNRELU>,
                             cudaFuncAttributeMaxDynamicSharedMemorySize, TC_SMEM);
        cudaFuncSetAttribute(gemm_mma128<EPI_BIAS2>,
                             cudaFuncAttributeMaxDynamicSharedMemorySize, TC_SMEM);
        init = true;
    }

    init_states<<<(B_ * L_ + 255) / 256, 256>>>();

    // ---- split fp32 -> bf16 hi/lo (phase-1 operands only) ----
    auto split = [](const float* s, __nv_bfloat16* h, __nv_bfloat16* l, size_t n) {
        int n4 = (int)(n / 4);
        splitf_kernel<<<(n4 + 255) / 256, 256>>>(s, h, l, n4);
    };
    split(x,     p_xhi,  p_xlo,  (size_t)BT_ * DIN_);
    split(xs,    p_xshi, p_xslo, (size_t)BT_ * DSM_);
    split(W_p,   p_wphi, p_wplo, (size_t)2048 * 2048);
    split(W_s,   p_wshi, p_wslo, (size_t)512 * 1280);
    split(Wih_l, p_wlhi, p_wllo, (size_t)4096 * 2560);
    split(Wih_s, p_wsihi, p_wsilo, (size_t)2048 * 512);

    // ---- phase 1: tensor-core split-bf16 GEMMs ----
    gemm_mma128<EPI_BNRELU><<<dim3(DIN_ / 128, BT_ / 128), 256, TC_SMEM>>>(
        p_xhi, p_xlo, DIN_, p_wphi, p_wplo, DIN_,
        nullptr, 0, p_cathi, p_catlo, DCAT_, b_p, g_p, be_p);
    gemm_mma128<EPI_BNRELU><<<dim3(S_ / 128, BT_ / 128), 256, TC_SMEM>>>(
        p_xshi, p_xslo, DSM_, p_wshi, p_wslo, DSM_,
        p_sf, S_, p_cathi + 2048, p_catlo + 2048, DCAT_, b_s, g_s, be_s);
    gemm_mma128<EPI_BIAS2><<<dim3(4096 / 128, BT_ / 128), 256, TC_SMEM>>>(
        p_cathi, p_catlo, DCAT_, p_wlhi, p_wllo, DCAT_,
        p_gl, 4096, nullptr, nullptr, 0, bih_l, bhh_l, nullptr);
    gemm_mma128<EPI_BIAS2><<<dim3(2048 / 128, BT_ / 128), 256, TC_SMEM>>>(
        p_cathi + 2048, p_catlo + 2048, DCAT_, p_wsihi, p_wsilo, S_,
        p_gs, 2048, nullptr, nullptr, 0, bih_s, bhh_s, nullptr);

    zs_kernel<<<BT_, 128>>>(W_g, b_g);

    // ---- phase 2: sequential recurrence (fp32 fused GEMM, 3 launches/step) ----
    for (int t = 0; t < T_; ++t) {
        gemm_p2_fused<<<dim3(96, B_ / 128), 256>>>(
            p_hl, p_hs, Whh_l, Whh_s, p_gatesL, p_gatesS, p_gl, p_gs, t);
        pw_small_gate<<<768, 256>>>(W_g, t, out_r);
        lstm_large_pw<<<(B_ * L_) / 256, 256>>>();
    }

    classifier_kernel<<<B_, 256>>>(W_c, b_c, out_logits);
}